// round 12
// baseline (speedup 1.0000x reference)
#include <cuda_runtime.h>
#include <cuda_bf16.h>
#include <cstdint>

#define NROWS 50000
#define KNB   32
#define CDIM  128
#define TOPK  16

// ---------------- scratch (device globals; no allocation) ----------------
__device__ __align__(16) float g_M [CDIM * CDIM];     // Wq^T @ Wk
__device__ __align__(16) float g_Ws[CDIM * CDIM];     // triu(W) + triu(W)^T
__device__ __align__(16) float g_qM[(size_t)NROWS * CDIM];  // feat @ M
__device__ __align__(16) float g_fW[(size_t)NROWS * CDIM];  // feat @ Ws
__device__ __align__(16) float g_scores[(size_t)NROWS * KNB];
__device__ int g_colmask[KNB];
__device__ int g_needfix;
__device__ int g_mask_narrow;   // 1 -> mask elements are 1 byte; 0 -> 4 bytes

// ---------------- packed f32x2 helpers ----------------
__device__ __forceinline__ unsigned long long pack2(float x, float y) {
    unsigned long long r;
    asm("mov.b64 %0, {%1, %2};" : "=l"(r) : "f"(x), "f"(y));
    return r;
}
__device__ __forceinline__ void fma2(unsigned long long& d,
                                     unsigned long long a, unsigned long long b) {
    asm("fma.rn.f32x2 %0, %1, %2, %0;" : "+l"(d) : "l"(a), "l"(b));
}
__device__ __forceinline__ float2 unpack2(unsigned long long v) {
    float2 r;
    asm("mov.b64 {%0, %1}, %2;" : "=f"(r.x), "=f"(r.y) : "l"(v));
    return r;
}

// ---------------- K0: prep M, Ws, reset flags ----------------
__global__ void prep_kernel(const float* __restrict__ Wq,
                            const float* __restrict__ Wk,
                            const float* __restrict__ W) {
    int c = blockIdx.x;    // 0..127
    int e = threadIdx.x;   // 0..127
    float acc = 0.f;
#pragma unroll 8
    for (int d = 0; d < CDIM; d++)
        acc += Wq[d * CDIM + c] * Wk[d * CDIM + e];
    g_M[c * CDIM + e] = acc;

    float w = (c <= e) ? W[c * CDIM + e] : W[e * CDIM + c];
    g_Ws[c * CDIM + e] = (c == e) ? 2.f * w : w;

    if (c == 0 && e < KNB) g_colmask[e] = 0;
    if (c == 0 && e == KNB) g_needfix = 0;
    if (c == 0 && e == KNB + 1) g_mask_narrow = 0;
}

// ---------------- K0b: sniff knn_mask element width ----------------
__global__ void sniff_kernel(const unsigned int* __restrict__ w) {
    const int nwords = NROWS * KNB / 4;
    int bad = 0;
    for (int i = blockIdx.x * blockDim.x + threadIdx.x; i < nwords;
         i += gridDim.x * blockDim.x) {
        unsigned int v = w[i];
        if (v != 0u && v != 1u && v != 0x3F800000u) bad = 1;
    }
    if (bad) g_mask_narrow = 1;
}

// ---------------- K1: SGEMM v5 — matrix-split + packed f32x2 FMA ----------------
// 64-row A tile in smem; threads 0-255 compute feat@M, 256-511 feat@Ws.
// Accumulators are packed f32x2 (FFMA2: 2 FMA/instr, bit-identical rounding).
__global__ void __launch_bounds__(512, 2) gemm_kernel(const float* __restrict__ A) {
    __shared__ __align__(16) float As[64 * 128];   // 32 KB

    int tid  = threadIdx.x;
    int half = tid >> 8;          // 0 -> M, 1 -> Ws
    int t    = tid & 255;
    int row0 = blockIdx.x * 64;

    for (int i = tid; i < 64 * 32; i += 512) {     // float4 units
        int r = i >> 5;
        float4 v = make_float4(0.f, 0.f, 0.f, 0.f);
        if (row0 + r < NROWS)
            v = reinterpret_cast<const float4*>(A)[(size_t)(row0 + r) * 32 + (i & 31)];
        reinterpret_cast<float4*>(As)[i] = v;
    }
    __syncthreads();

    const float* __restrict__ B   = half ? g_Ws : g_M;
    float*       __restrict__ Out = half ? g_fW : g_qM;

    int cq = t & 15;   // cols cq*8 .. cq*8+7
    int rg = t >> 4;   // rows rg*4 .. rg*4+3
    unsigned long long acc[4][4];                  // [row][col-pair]
#pragma unroll
    for (int i = 0; i < 4; i++)
#pragma unroll
        for (int p = 0; p < 4; p++) acc[i][p] = 0ull;

    const float* Arow = As + rg * 4 * 128;
#pragma unroll 4
    for (int k = 0; k < 128; k++) {
        unsigned long long a2[4];
#pragma unroll
        for (int i = 0; i < 4; i++) {
            float a = Arow[i * 128 + k];
            a2[i] = pack2(a, a);
        }
        float4 b0 = __ldg((const float4*)(B + k * 128 + cq * 8));
        float4 b1 = __ldg((const float4*)(B + k * 128 + cq * 8 + 4));
        unsigned long long b2[4] = { pack2(b0.x, b0.y), pack2(b0.z, b0.w),
                                     pack2(b1.x, b1.y), pack2(b1.z, b1.w) };
#pragma unroll
        for (int i = 0; i < 4; i++)
#pragma unroll
            for (int p = 0; p < 4; p++) fma2(acc[i][p], a2[i], b2[p]);
    }

#pragma unroll
    for (int i = 0; i < 4; i++) {
        int r = row0 + rg * 4 + i;
        if (r < NROWS) {
            float2 u0 = unpack2(acc[i][0]), u1 = unpack2(acc[i][1]);
            float2 u2 = unpack2(acc[i][2]), u3 = unpack2(acc[i][3]);
            float4* p = reinterpret_cast<float4*>(Out + (size_t)r * 128 + cq * 8);
            p[0] = make_float4(u0.x, u0.y, u1.x, u1.y);
            p[1] = make_float4(u2.x, u2.y, u3.x, u3.y);
        }
    }
}

// ---------------- K2: warp-per-row streaming kernel ----------------
// One warp owns a row end-to-end: dots (batched shuffle reduce), then
// lane==neighbor for mask/rank/colmask/softmax (all warp-local), then wsum
// with attn shuffle-broadcast and kf re-read (L2 hit). No barriers, no smem.
__global__ void __launch_bounds__(256, 5) main_kernel(
    const float* __restrict__ feat, const float* __restrict__ knn_xyz,
    const float* __restrict__ knn_feat, const void* __restrict__ knn_mask,
    float* __restrict__ out_xyz, float* __restrict__ out_att, float* __restrict__ out_ml)
{
    int tid  = threadIdx.x;
    int warp = tid >> 5;
    int lane = tid & 31;
    int n    = blockIdx.x * 8 + warp;

    const float4* kf4 = reinterpret_cast<const float4*>(knn_feat + (size_t)n * (KNB * CDIM));
    float4 qv = __ldg(reinterpret_cast<const float4*>(g_qM + (size_t)n * CDIM) + lane);
    float4 fv = __ldg(reinterpret_cast<const float4*>(g_fW + (size_t)n * CDIM) + lane);

    // lane j's mask adjust + xyz triplet
    float madj;
    if (g_mask_narrow)
        madj = ((const unsigned char*)knn_mask)[(size_t)n * KNB + lane] ? 0.f : -1e12f;
    else
        madj = ((const unsigned int*)knn_mask)[(size_t)n * KNB + lane] ? 0.f : -1e12f;
    float xj0 = __ldg(&knn_xyz[(size_t)n * 96 + lane * 3    ]);
    float xj1 = __ldg(&knn_xyz[(size_t)n * 96 + lane * 3 + 1]);
    float xj2 = __ldg(&knn_xyz[(size_t)n * 96 + lane * 3 + 2]);

    // dots: 8 batches of 4 neighbors; lane c-quad = lane*4..lane*4+3
    float myS = 0.f, myMl = 0.f;
#pragma unroll
    for (int b = 0; b < 8; b++) {
        float s[4], ml[4];
#pragma unroll
        for (int jj = 0; jj < 4; jj++) {
            float4 k4 = __ldg(kf4 + (b * 4 + jj) * 32 + lane);
            s [jj] = k4.x * qv.x + k4.y * qv.y + k4.z * qv.z + k4.w * qv.w;
            ml[jj] = k4.x * fv.x + k4.y * fv.y + k4.z * fv.z + k4.w * fv.w;
        }
#pragma unroll
        for (int o = 16; o; o >>= 1) {
#pragma unroll
            for (int jj = 0; jj < 4; jj++) {
                s [jj] += __shfl_xor_sync(0xffffffffu, s [jj], o);
                ml[jj] += __shfl_xor_sync(0xffffffffu, ml[jj], o);
            }
        }
#pragma unroll
        for (int jj = 0; jj < 4; jj++) {
            if (lane == b * 4 + jj) { myS = s[jj]; myMl = ml[jj]; }
        }
    }
    myS += madj;

    // rank (lax.top_k stable tie rule) — warp-local
    int rank = 0;
#pragma unroll
    for (int i = 0; i < KNB; i++) {
        float si = __shfl_sync(0xffffffffu, myS, i);
        rank += (si > myS) || (si == myS && i < lane);
    }
    if (rank < TOPK) {
        if (__ldcg(&g_colmask[lane]) == 0) atomicOr(&g_colmask[lane], 1);
    }
    g_scores[(size_t)n * KNB + lane] = myS;
    out_ml[(size_t)n * KNB + lane]   = myMl;

    // softmax — warp-local
    float m = myS;
#pragma unroll
    for (int o = 16; o; o >>= 1) m = fmaxf(m, __shfl_xor_sync(0xffffffffu, m, o));
    float e = __expf(myS - m);
    float ssum = e;
#pragma unroll
    for (int o = 16; o; o >>= 1) ssum += __shfl_xor_sync(0xffffffffu, ssum, o);
    float attn = e / ssum;

    // weighted sum: attn broadcast, kf re-read (L2 hits), lane -> channel quad
    float4 acc4 = make_float4(0.f, 0.f, 0.f, 0.f);
#pragma unroll
    for (int j = 0; j < KNB; j++) {
        float  a  = __shfl_sync(0xffffffffu, attn, j);
        float4 k4 = __ldg(kf4 + j * 32 + lane);
        acc4.x += a * k4.x; acc4.y += a * k4.y; acc4.z += a * k4.z; acc4.w += a * k4.w;
    }

    // xyz: lane j holds attn_j * xyz_j, butterfly-reduce 3 components
    float x0 = attn * xj0, x1 = attn * xj1, x2 = attn * xj2;
#pragma unroll
    for (int o = 16; o; o >>= 1) {
        x0 += __shfl_xor_sync(0xffffffffu, x0, o);
        x1 += __shfl_xor_sync(0xffffffffu, x1, o);
        x2 += __shfl_xor_sync(0xffffffffu, x2, o);
    }

    // outputs
    size_t ob = (size_t)n * 257;
    float4 f4 = __ldg(reinterpret_cast<const float4*>(feat + (size_t)n * CDIM) + lane);
    out_att[ob + lane * 4    ] = f4.x;
    out_att[ob + lane * 4 + 1] = f4.y;
    out_att[ob + lane * 4 + 2] = f4.z;
    out_att[ob + lane * 4 + 3] = f4.w;
    out_att[ob + 128 + lane * 4    ] = acc4.x;
    out_att[ob + 128 + lane * 4 + 1] = acc4.y;
    out_att[ob + 128 + lane * 4 + 2] = acc4.z;
    out_att[ob + 128 + lane * 4 + 3] = acc4.w;

    float p = fv.x * acc4.x + fv.y * acc4.y + fv.z * acc4.z + fv.w * acc4.w;
#pragma unroll
    for (int o = 16; o; o >>= 1) p += __shfl_xor_sync(0xffffffffu, p, o);
    if (lane == 0) {
        out_att[ob + 256] = p;                  // logit
        out_xyz[(size_t)n * 3    ] = x0;
        out_xyz[(size_t)n * 3 + 1] = x1;
        out_xyz[(size_t)n * 3 + 2] = x2;
    }
}

// ---------------- K3: check whether any column never made top-k ----------------
__global__ void check_kernel() {
    int t = threadIdx.x;
    int miss = (t < KNB && g_colmask[t] == 0) ? 1 : 0;
#pragma unroll
    for (int o = 16; o; o >>= 1) miss |= __shfl_xor_sync(0xffffffffu, miss, o);
    if (t == 0) g_needfix = miss;
}

// ---------------- K4: fixup (early-exits when colmask is all-covered) ----------------
__global__ void __launch_bounds__(128) fixup_kernel(
    const float* __restrict__ knn_feat, const float* __restrict__ knn_xyz,
    float* __restrict__ out_xyz, float* __restrict__ out_att)
{
    if (g_needfix == 0) return;   // common case

    __shared__ float attnS[KNB];
    __shared__ float redS[4];
    __shared__ int   colS[KNB];
    int tid = threadIdx.x, lane = tid & 31, warp = tid >> 5;
    if (tid < KNB) colS[tid] = g_colmask[tid];
    __syncthreads();

    for (int n = blockIdx.x; n < NROWS; n += gridDim.x) {
        if (tid < KNB) {
            float s  = g_scores[(size_t)n * KNB + tid];
            int inc  = colS[tid];
            float se = inc ? s : -3.0e38f;
            float m = se;
#pragma unroll
            for (int o = 16; o; o >>= 1) m = fmaxf(m, __shfl_xor_sync(0xffffffffu, m, o));
            float e = inc ? __expf(se - m) : 0.f;
            float ssum = e;
#pragma unroll
            for (int o = 16; o; o >>= 1) ssum += __shfl_xor_sync(0xffffffffu, ssum, o);
            attnS[tid] = e / ssum;
        }
        __syncthreads();

        float acc = 0.f;
#pragma unroll
        for (int j = 0; j < KNB; j++)
            acc += attnS[j] * knn_feat[(size_t)n * (KNB * CDIM) + j * CDIM + tid];

        size_t ob = (size_t)n * 257;
        out_att[ob + 128 + tid] = acc;

        float p = g_fW[(size_t)n * CDIM + tid] * acc;
#pragma unroll
        for (int o = 16; o; o >>= 1) p += __shfl_xor_sync(0xffffffffu, p, o);
        if (lane == 0) redS[warp] = p;
        __syncthreads();
        if (tid == 0) out_att[ob + 256] = redS[0] + redS[1] + redS[2] + redS[3];

        if (tid < 3) {
            float x = 0.f;
#pragma unroll
            for (int j = 0; j < KNB; j++)
                x += attnS[j] * knn_xyz[(size_t)n * (KNB * 3) + j * 3 + tid];
            out_xyz[(size_t)n * 3 + tid] = x;
        }
        __syncthreads();
    }
}

// ---------------- launch ----------------
extern "C" void kernel_launch(void* const* d_in, const int* in_sizes, int n_in,
                              void* d_out, int out_size) {
    const float* feat     = (const float*)d_in[0];          // [N,128]
    const float* knn_xyz  = (const float*)d_in[1];          // [N,32,3]
    const float* knn_feat = (const float*)d_in[2];          // [N,32,128]
    const void*  knn_mask = d_in[3];                        // [N,32] bool (width sniffed)
    const float* Wq       = (const float*)d_in[4];          // [128,128]
    const float* Wk       = (const float*)d_in[5];          // [128,128]
    const float* W        = (const float*)d_in[6];          // [128,128]

    float* out     = (float*)d_out;
    float* out_xyz = out;                                   // [N,3]
    float* out_att = out + (size_t)NROWS * 3;               // [N,257]
    float* out_ml  = out + (size_t)NROWS * 3 + (size_t)NROWS * 257;  // [N,32]

    prep_kernel<<<CDIM, CDIM>>>(Wq, Wk, W);
    sniff_kernel<<<512, 256>>>((const unsigned int*)knn_mask);

    gemm_kernel<<<(NROWS + 63) / 64, 512>>>(feat);

    main_kernel<<<NROWS / 8, 256>>>(feat, knn_xyz, knn_feat, knn_mask,
                                    out_xyz, out_att, out_ml);

    check_kernel<<<1, 32>>>();
    fixup_kernel<<<2048, CDIM>>>(knn_feat, knn_xyz, out_xyz, out_att);
}